// round 12
// baseline (speedup 1.0000x reference)
#include <cuda_runtime.h>
#include <cuda_bf16.h>
#include <cstdint>

// Problem constants
#define B_   8
#define L_   2048
#define DM_  512
#define NH_  8
#define DK_  64
#define BH_  (B_*NH_)            // 64
// Q pre-scale: (1/sqrt(DK)) * log2(e), so epilogue is ex2.approx
#define QSCALE 0.18033688011112043f

#define TILE_W 36                 // words per smem row (Q/K tiles)
#define TILE_WORDS (128 * TILE_W) // 4608 words = 18432 B per tile
#define EW 68                     // words per sE staging row (64 data + pad)

// Scratch (device globals; allocation-free kernel_launch)
__device__ __nv_bfloat16 g_Qh[BH_ * L_ * DK_];   // bf16, pre-scaled by QSCALE
__device__ __nv_bfloat16 g_Kh[BH_ * L_ * DK_];   // bf16
__device__ __nv_bfloat16 g_E[(size_t)BH_ * L_ * L_]; // 536 MB: exp2(S)
__device__ float g_ell[BH_ * L_];                // row sums of exp2(S)
__device__ float g_P[BH_ * L_];                  // pooled = colmean of softmax
__device__ float g_z[B_ * NH_ * DM_];            // z[b,h,m] = sum_k P*x
__device__ float g_res[B_ * DM_];                // sum over L of x (residual*L)

// ---------------------------------------------------------------------------
// Helpers
// ---------------------------------------------------------------------------
__device__ __forceinline__ float fast_exp2(float x) {
    float r;
    asm("ex2.approx.f32 %0, %1;" : "=f"(r) : "f"(x));
    return r;
}
__device__ __forceinline__ uint32_t pack_bf162(float lo, float hi) {
    uint32_t r;
    asm("cvt.rn.bf16x2.f32 %0, %1, %2;" : "=r"(r) : "f"(hi), "f"(lo));
    return r;
}
__device__ __forceinline__ void mma_bf16(float c[4],
    uint32_t a0, uint32_t a1, uint32_t a2, uint32_t a3,
    uint32_t b0, uint32_t b1)
{
    asm volatile(
        "mma.sync.aligned.m16n8k16.row.col.f32.bf16.bf16.f32 "
        "{%0,%1,%2,%3}, {%4,%5,%6,%7}, {%8,%9}, {%0,%1,%2,%3};\n"
        : "+f"(c[0]), "+f"(c[1]), "+f"(c[2]), "+f"(c[3])
        : "r"(a0), "r"(a1), "r"(a2), "r"(a3), "r"(b0), "r"(b1));
}
__device__ __forceinline__ void ldsm_x4(uint32_t& r0, uint32_t& r1,
                                        uint32_t& r2, uint32_t& r3,
                                        uint32_t addr)
{
    asm volatile("ldmatrix.sync.aligned.m8n8.x4.shared.b16 {%0,%1,%2,%3}, [%4];"
                 : "=r"(r0), "=r"(r1), "=r"(r2), "=r"(r3) : "r"(addr));
}
__device__ __forceinline__ uint32_t smem_u32(const void* p) {
    return (uint32_t)__cvta_generic_to_shared(p);
}
__device__ __forceinline__ void cp16(uint32_t dst, const void* src) {
    asm volatile("cp.async.cg.shared.global [%0], [%1], 16;\n"
                 :: "r"(dst), "l"(src));
}
__device__ __forceinline__ void cp_commit() {
    asm volatile("cp.async.commit_group;\n" ::: "memory");
}
__device__ __forceinline__ void cp_wait1() {
    asm volatile("cp.async.wait_group 1;\n" ::: "memory");
}
__device__ __forceinline__ void cp_wait0() {
    asm volatile("cp.async.wait_group 0;\n" ::: "memory");
}

// ---------------------------------------------------------------------------
// Shared bf16 MMA tile core (unchanged; validated R7-R11)
// ---------------------------------------------------------------------------
__device__ __forceinline__ void mma_tile_core(
    uint32_t sQb, uint32_t sKb, int wm, int wn, int lane, float acc[2][8][4])
{
    const uint32_t a_off =
        sQb + (((wm * 32 + (lane & 15)) * TILE_W + (lane >> 4) * 4) << 2);
    const uint32_t b_off =
        sKb + (((wn * 64 + ((lane >> 4) << 3) + (lane & 7)) * TILE_W
                + ((lane >> 3) & 1) * 4) << 2);
    #pragma unroll
    for (int k0w = 0; k0w < 32; k0w += 8) {
        uint32_t a[2][4], b[8][2];
        #pragma unroll
        for (int i = 0; i < 2; i++)
            ldsm_x4(a[i][0], a[i][1], a[i][2], a[i][3],
                    a_off + ((i * 16 * TILE_W + k0w) << 2));
        #pragma unroll
        for (int jp = 0; jp < 4; jp++)
            ldsm_x4(b[2 * jp][0], b[2 * jp][1], b[2 * jp + 1][0], b[2 * jp + 1][1],
                    b_off + ((jp * 16 * TILE_W + k0w) << 2));
        #pragma unroll
        for (int i = 0; i < 2; i++)
            #pragma unroll
            for (int j = 0; j < 8; j++)
                mma_bf16(acc[i][j], a[i][0], a[i][1], a[i][2], a[i][3],
                         b[j][0], b[j][1]);
    }
}

// Issue the 4 cp.async for this thread's share of one 128x64 bf16 tile.
__device__ __forceinline__ void tile_cp_async(
    uint32_t dstb, const uint32_t* src, int row, int w4)
{
    #pragma unroll
    for (int p = 0; p < 4; p++)
        cp16(dstb + (((row + 32 * p) * TILE_W + w4) << 2),
             src + (row + 32 * p) * 32 + w4);
    cp_commit();
}

// ---------------------------------------------------------------------------
// Kernel 0: zero accumulated buffers (g_P, g_z, g_res)
// ---------------------------------------------------------------------------
__global__ void zero_kernel() {
    int i = blockIdx.x * 256 + threadIdx.x;
    if (i < BH_ * L_) g_P[i] = 0.f;
    if (i < B_ * NH_ * DM_) g_z[i] = 0.f;
    if (i < B_ * DM_) g_res[i] = 0.f;
}

// ---------------------------------------------------------------------------
// Kernel 1: Q/K projection via bf16 mma. C[16384,1024] = x @ [w_q;w_k]^T
// ---------------------------------------------------------------------------
__global__ __launch_bounds__(256) void proj_kernel(
    const float* __restrict__ x,
    const float* __restrict__ wq,
    const float* __restrict__ wk)
{
    __shared__ uint32_t sA[TILE_WORDS];
    __shared__ uint32_t sB[TILE_WORDS];
    const int t = threadIdx.x;
    const int m0 = blockIdx.y << 7;
    const int n0 = blockIdx.x << 7;
    const int wid = t >> 5, lane = t & 31;
    const int wm = wid >> 1, wn = wid & 1;
    const int g = lane >> 2, tq = lane & 3;
    const uint32_t sAb = smem_u32(sA), sBb = smem_u32(sB);

    float acc[2][8][4] = {};

    #pragma unroll 1
    for (int kc = 0; kc < 8; kc++) {
        #pragma unroll
        for (int f = t; f < 2048; f += 256) {
            int row = f >> 4, q4 = f & 15;
            float4 av = *(const float4*)(
                x + (size_t)(m0 + row) * DM_ + kc * 64 + q4 * 4);
            sA[row * TILE_W + q4 * 2]     = pack_bf162(av.x, av.y);
            sA[row * TILE_W + q4 * 2 + 1] = pack_bf162(av.z, av.w);
            int n = n0 + row;
            const float* src = (n < 512) ? (wq + (size_t)n * DM_)
                                         : (wk + (size_t)(n - 512) * DM_);
            float4 bv = *(const float4*)(src + kc * 64 + q4 * 4);
            sB[row * TILE_W + q4 * 2]     = pack_bf162(bv.x, bv.y);
            sB[row * TILE_W + q4 * 2 + 1] = pack_bf162(bv.z, bv.w);
        }
        __syncthreads();
        mma_tile_core(sAb, sBb, wm, wn, lane, acc);
        __syncthreads();
    }

    #pragma unroll
    for (int i = 0; i < 2; i++) {
        #pragma unroll
        for (int rr = 0; rr < 2; rr++) {
            int r = m0 + wm * 32 + i * 16 + g + rr * 8;
            int bidx = r >> 11, l = r & 2047;
            #pragma unroll
            for (int j = 0; j < 8; j++) {
                int n = n0 + wn * 64 + j * 8 + 2 * tq;
                float v0 = acc[i][j][rr * 2 + 0];
                float v1 = acc[i][j][rr * 2 + 1];
                if (n < 512) {
                    int h = n >> 6, d = n & 63;
                    *(uint32_t*)&g_Qh[(((size_t)(bidx << 3) + h) * L_ + l) * DK_ + d] =
                        pack_bf162(v0 * QSCALE, v1 * QSCALE);
                } else {
                    int n2 = n - 512;
                    int h = n2 >> 6, d = n2 & 63;
                    *(uint32_t*)&g_Kh[(((size_t)(bidx << 3) + h) * L_ + l) * DK_ + d] =
                        pack_bf162(v0, v1);
                }
            }
        }
    }
}

// ---------------------------------------------------------------------------
// Kernel 2: pass 1 — q-strip persistent. Computes S once, exp2, row sums
// (direct store, no atomics) AND stages/stores E tiles coalesced to g_E.
// dyn smem: [sQ | sK0 | sK1 | sE(128x68 words)]
// ---------------------------------------------------------------------------
__global__ __launch_bounds__(256) void attn_pass1_kernel()
{
    extern __shared__ uint32_t dyn[];
    uint32_t* sQ = dyn;
    uint32_t* sK0 = dyn + TILE_WORDS;
    uint32_t* sE = dyn + 3 * TILE_WORDS;
    __shared__ float rsum[2][128];
    const int t = threadIdx.x;
    const int q0 = blockIdx.x << 7;
    const int bh = blockIdx.y;
    const int wid = t >> 5, lane = t & 31;
    const int wm = wid >> 1, wn = wid & 1;
    const int g = lane >> 2, tq = lane & 3;
    const int row = t >> 3, w4 = (t & 7) << 2;

    const uint32_t* qsrc =
        (const uint32_t*)(g_Qh + (size_t)bh * L_ * DK_ + (size_t)q0 * DK_);
    const uint32_t* kbase = (const uint32_t*)(g_Kh + (size_t)bh * L_ * DK_);
    #pragma unroll
    for (int f = t; f < 1024; f += 256) {
        int rr = f >> 3, ww = (f & 7) << 2;
        *(uint4*)&sQ[rr * TILE_W + ww] = *(const uint4*)(qsrc + rr * 32 + ww);
    }

    const uint32_t sQb = smem_u32(sQ);
    const uint32_t sKb[2] = { smem_u32(sK0), smem_u32(sK0 + TILE_WORDS) };

    tile_cp_async(sKb[0], kbase, row, w4);   // tile 0 in flight

    float rs[2][2] = {};
    __nv_bfloat16* erow = g_E + (size_t)(bh * L_ + q0) * L_;

    #pragma unroll 1
    for (int kt = 0; kt < 16; kt++) {
        if (kt < 15) {
            tile_cp_async(sKb[(kt + 1) & 1], kbase + (kt + 1) * 4096, row, w4);
            cp_wait1();
        } else {
            cp_wait0();
        }
        __syncthreads();
        float acc[2][8][4] = {};
        mma_tile_core(sQb, sKb[kt & 1], wm, wn, lane, acc);

        // exp2, row-sum accumulate, stage tile in sE (conflict-free STS)
        #pragma unroll
        for (int i = 0; i < 2; i++) {
            int r0 = wm * 32 + i * 16 + g;
            #pragma unroll
            for (int j = 0; j < 8; j++) {
                float e0 = fast_exp2(acc[i][j][0]);
                float e1 = fast_exp2(acc[i][j][1]);
                float e2 = fast_exp2(acc[i][j][2]);
                float e3 = fast_exp2(acc[i][j][3]);
                rs[i][0] += e0 + e1;
                rs[i][1] += e2 + e3;
                int colw = wn * 32 + j * 4 + tq;
                sE[r0 * EW + colw]       = pack_bf162(e0, e1);
                sE[(r0 + 8) * EW + colw] = pack_bf162(e2, e3);
            }
        }
        __syncthreads();
        // cooperative coalesced store of the staged tile: 128 rows x 256 B
        {
            __nv_bfloat16* dst = erow + kt * 128;
            #pragma unroll
            for (int idx = t; idx < 4096; idx += 256) {
                int r = idx >> 5, w2 = idx & 31;
                uint2 v = *(uint2*)&sE[r * EW + w2 * 2];
                *(uint2*)(dst + (size_t)r * L_ + w2 * 4) = v;
            }
        }
        __syncthreads();   // protect sK + sE reuse next iteration
    }

    // reduce over tq lanes and wn warps; direct store to g_ell
    #pragma unroll
    for (int i = 0; i < 2; i++) {
        #pragma unroll
        for (int rr = 0; rr < 2; rr++) {
            float s = rs[i][rr];
            s += __shfl_xor_sync(0xffffffffu, s, 1);
            s += __shfl_xor_sync(0xffffffffu, s, 2);
            if ((lane & 3) == 0)
                rsum[wn][wm * 32 + i * 16 + rr * 8 + g] = s;
        }
    }
    __syncthreads();
    if (t < 128)
        g_ell[bh * L_ + q0 + t] = rsum[0][t] + rsum[1][t];
}

// ---------------------------------------------------------------------------
// Kernel 3: pass 2 — pooled P = (1/L) colsum of E/ell. Pure streaming reader
// (measured 73-75% DRAM in R2/R4).
// ---------------------------------------------------------------------------
__global__ __launch_bounds__(256) void colsum_kernel()
{
    __shared__ float sinv[128];
    const int qc = blockIdx.x;
    const int bh = blockIdx.y;
    const int t  = threadIdx.x;
    if (t < 128)
        sinv[t] = 1.0f / g_ell[bh * L_ + (qc << 7) + t];
    __syncthreads();

    float acc[8] = {};
    const __nv_bfloat16* base =
        g_E + ((size_t)(bh * L_) + (qc << 7)) * L_ + (t << 3);
    #pragma unroll 8
    for (int q = 0; q < 128; q++) {
        uint4 v = *(const uint4*)(base + (size_t)q * L_);
        float r = sinv[q];
        const __nv_bfloat162* pv = reinterpret_cast<const __nv_bfloat162*>(&v);
        #pragma unroll
        for (int p = 0; p < 4; p++) {
            float2 f = __bfloat1622float2(pv[p]);
            acc[2 * p]     += r * f.x;
            acc[2 * p + 1] += r * f.y;
        }
    }
    #pragma unroll
    for (int j = 0; j < 8; j++)
        atomicAdd(&g_P[bh * L_ + (t << 3) + j], acc[j] * (1.0f / (float)L_));
}

// ---------------------------------------------------------------------------
// Kernel 4: z[b,h,m] = sum_l P[b,h,l]*x[b,l,m]; residual sums
// ---------------------------------------------------------------------------
__global__ __launch_bounds__(512) void zres_kernel(const float* __restrict__ x)
{
    __shared__ float Ps[8][128];
    const int lc = blockIdx.x;
    const int b  = blockIdx.y;
    const int t  = threadIdx.x;
    for (int i = t; i < 1024; i += 512) {
        int h = i >> 7, l = i & 127;
        Ps[h][l] = g_P[((b << 3) + h) * L_ + (lc << 7) + l];
    }
    __syncthreads();

    float zacc[8] = {};
    float racc = 0.f;
    const float* xb = x + ((size_t)b * L_ + (size_t)(lc << 7)) * DM_ + t;
    #pragma unroll 4
    for (int ll = 0; ll < 128; ll++) {
        float xv = xb[(size_t)ll * DM_];
        racc += xv;
        #pragma unroll
        for (int h = 0; h < 8; h++)
            zacc[h] += Ps[h][ll] * xv;
    }
    atomicAdd(&g_res[(b << 9) + t], racc);
    #pragma unroll
    for (int h = 0; h < 8; h++)
        atomicAdd(&g_z[(((b << 3) + h) << 9) + t], zacc[h]);
}

// ---------------------------------------------------------------------------
// Kernel 5: attn_ret, out = z@w_v^T/L, flat@w_fc^T + residual, layernorm
// ---------------------------------------------------------------------------
__global__ __launch_bounds__(512) void finalize_kernel(
    const float* __restrict__ w_v,
    const float* __restrict__ w_fc,
    const float* __restrict__ gamma,
    const float* __restrict__ beta,
    float* __restrict__ out)
{
    __shared__ float zsh[4096];
    __shared__ float flat[512];
    __shared__ float rs[16], rq[16];
    __shared__ float stats[2];
    const int b = blockIdx.x;
    const int t = threadIdx.x;

    for (int i = t; i < 4096; i += 512)
        zsh[i] = g_z[(size_t)b * 4096 + i];

    for (int k = t; k < L_; k += 512) {
        float s = 0.f;
        #pragma unroll
        for (int h = 0; h < 8; h++)
            s += g_P[((b << 3) + h) * L_ + k];
        out[4096 + b * L_ + k] = s * 0.125f;
    }
    __syncthreads();

    {
        const int h = t >> 6, dv = t & 63;
        const float4* wv4 = (const float4*)(w_v + (size_t)((h << 6) + dv) * DM_);
        const float4* z4  = (const float4*)(zsh + (h << 9));
        float ov = 0.f;
        #pragma unroll 8
        for (int m = 0; m < DM_ / 4; m++) {
            float4 a = z4[m], w = wv4[m];
            ov += a.x * w.x + a.y * w.y + a.z * w.z + a.w * w.w;
        }
        flat[(dv << 3) + h] = ov * (1.0f / (float)L_);
    }
    __syncthreads();

    float acc = g_res[(b << 9) + t] * (1.0f / (float)L_);
    {
        const float4* wf4 = (const float4*)(w_fc + (size_t)t * DM_);
        const float4* f4  = (const float4*)flat;
        #pragma unroll 8
        for (int m = 0; m < DM_ / 4; m++) {
            float4 f = f4[m], w = wf4[m];
            acc += f.x * w.x + f.y * w.y + f.z * w.z + f.w * w.w;
        }
    }

    float s1 = acc, s2 = acc * acc;
    #pragma unroll
    for (int off = 16; off; off >>= 1) {
        s1 += __shfl_xor_sync(0xffffffffu, s1, off);
        s2 += __shfl_xor_sync(0xffffffffu, s2, off);
    }
    if ((t & 31) == 0) { rs[t >> 5] = s1; rq[t >> 5] = s2; }
    __syncthreads();
    if (t == 0) {
        float S = 0.f, Q2 = 0.f;
        #pragma unroll
        for (int i = 0; i < 16; i++) { S += rs[i]; Q2 += rq[i]; }
        float mu  = S * (1.0f / 512.0f);
        float var = Q2 * (1.0f / 512.0f) - mu * mu;
        stats[0] = mu;
        stats[1] = rsqrtf(var + 1e-6f);
    }
    __syncthreads();
    out[(b << 9) + t] = (acc - stats[0]) * stats[1] * gamma[t] + beta[t];
}

// ---------------------------------------------------------------------------
extern "C" void kernel_launch(void* const* d_in, const int* in_sizes, int n_in,
                              void* d_out, int out_size)
{
    (void)in_sizes; (void)n_in; (void)out_size;
    const float* x     = (const float*)d_in[0];
    const float* w_q   = (const float*)d_in[1];
    const float* w_k   = (const float*)d_in[2];
    const float* w_v   = (const float*)d_in[3];
    const float* w_fc  = (const float*)d_in[4];
    const float* gamma = (const float*)d_in[5];
    const float* beta  = (const float*)d_in[6];
    float* out = (float*)d_out;

    const int p1_smem = (3 * TILE_WORDS + 128 * EW) * 4;   // 90112 B
    cudaFuncSetAttribute(attn_pass1_kernel,
                         cudaFuncAttributeMaxDynamicSharedMemorySize, p1_smem);

    zero_kernel<<<512, 256>>>();
    proj_kernel<<<dim3(8, 128), 256>>>(x, w_q, w_k);
    attn_pass1_kernel<<<dim3(16, 64), 256, p1_smem>>>();
    colsum_kernel<<<dim3(16, 64), 256>>>();
    zres_kernel<<<dim3(16, 8), 512>>>(x);
    finalize_kernel<<<8, 512>>>(w_v, w_fc, gamma, beta, out);
}

// round 14
// speedup vs baseline: 1.0743x; 1.0743x over previous
#include <cuda_runtime.h>
#include <cuda_bf16.h>
#include <cstdint>

// Problem constants
#define B_   8
#define L_   2048
#define DM_  512
#define NH_  8
#define DK_  64
#define BH_  (B_*NH_)            // 64
// Q pre-scale: (1/sqrt(DK)) * log2(e), so epilogue is ex2.approx
#define QSCALE 0.18033688011112043f

#define TILE_W 36                 // words per smem row
#define TILE_WORDS (128 * TILE_W) // full 128-row tile
#define HBUF_WORDS (64 * TILE_W)  // half tile (64 rows)
// attention dyn smem layout: resident full tile + 2 groups x 2 half buffers
#define OFF_HB(g, b) (TILE_WORDS + ((g) * 2 + (b)) * HBUF_WORDS)
#define ATTN_SMEM ((TILE_WORDS + 4 * HBUF_WORDS) * 4)   // 55296 B

// Scratch (device globals; allocation-free kernel_launch)
__device__ __nv_bfloat16 g_Qh[BH_ * L_ * DK_];   // bf16, pre-scaled by QSCALE
__device__ __nv_bfloat16 g_Kh[BH_ * L_ * DK_];   // bf16
__device__ float g_ell[BH_ * L_];                // row sums of exp2(S)
__device__ float g_P[BH_ * L_];                  // pooled = colmean of softmax
__device__ float g_z[B_ * NH_ * DM_];            // z[b,h,m] = sum_k P*x
__device__ float g_res[B_ * DM_];                // sum over L of x (residual*L)

// ---------------------------------------------------------------------------
// Helpers
// ---------------------------------------------------------------------------
__device__ __forceinline__ float fast_exp2(float x) {
    float r;
    asm("ex2.approx.f32 %0, %1;" : "=f"(r) : "f"(x));
    return r;
}
__device__ __forceinline__ uint32_t pack_bf162(float lo, float hi) {
    uint32_t r;
    asm("cvt.rn.bf16x2.f32 %0, %1, %2;" : "=r"(r) : "f"(hi), "f"(lo));
    return r;
}
__device__ __forceinline__ void mma_bf16(float c[4],
    uint32_t a0, uint32_t a1, uint32_t a2, uint32_t a3,
    uint32_t b0, uint32_t b1)
{
    asm volatile(
        "mma.sync.aligned.m16n8k16.row.col.f32.bf16.bf16.f32 "
        "{%0,%1,%2,%3}, {%4,%5,%6,%7}, {%8,%9}, {%0,%1,%2,%3};\n"
        : "+f"(c[0]), "+f"(c[1]), "+f"(c[2]), "+f"(c[3])
        : "r"(a0), "r"(a1), "r"(a2), "r"(a3), "r"(b0), "r"(b1));
}
__device__ __forceinline__ void ldsm_x4(uint32_t& r0, uint32_t& r1,
                                        uint32_t& r2, uint32_t& r3,
                                        uint32_t addr)
{
    asm volatile("ldmatrix.sync.aligned.m8n8.x4.shared.b16 {%0,%1,%2,%3}, [%4];"
                 : "=r"(r0), "=r"(r1), "=r"(r2), "=r"(r3) : "r"(addr));
}
__device__ __forceinline__ uint32_t smem_u32(const void* p) {
    return (uint32_t)__cvta_generic_to_shared(p);
}
__device__ __forceinline__ void cp16(uint32_t dst, const void* src) {
    asm volatile("cp.async.cg.shared.global [%0], [%1], 16;\n"
                 :: "r"(dst), "l"(src));
}
__device__ __forceinline__ void cp_commit() {
    asm volatile("cp.async.commit_group;\n" ::: "memory");
}
__device__ __forceinline__ void cp_wait1() {
    asm volatile("cp.async.wait_group 1;\n" ::: "memory");
}
__device__ __forceinline__ void cp_wait0() {
    asm volatile("cp.async.wait_group 0;\n" ::: "memory");
}
__device__ __forceinline__ void gbar(int id) {
    asm volatile("bar.sync %0, 128;" :: "r"(id) : "memory");
}

// ---------------------------------------------------------------------------
// Shared bf16 MMA tile core: warp tile 32(q) x 64(k), depth 64 (4 k16 steps).
// Works for both full 128-row buffers and 64-row half buffers as long as
// (wm*32 + 31) and (wn*64 + 63) stay inside the buffer.
// ---------------------------------------------------------------------------
__device__ __forceinline__ void mma_tile_core(
    uint32_t sQb, uint32_t sKb, int wm, int wn, int lane, float acc[2][8][4])
{
    const uint32_t a_off =
        sQb + (((wm * 32 + (lane & 15)) * TILE_W + (lane >> 4) * 4) << 2);
    const uint32_t b_off =
        sKb + (((wn * 64 + ((lane >> 4) << 3) + (lane & 7)) * TILE_W
                + ((lane >> 3) & 1) * 4) << 2);
    #pragma unroll
    for (int k0w = 0; k0w < 32; k0w += 8) {
        uint32_t a[2][4], b[8][2];
        #pragma unroll
        for (int i = 0; i < 2; i++)
            ldsm_x4(a[i][0], a[i][1], a[i][2], a[i][3],
                    a_off + ((i * 16 * TILE_W + k0w) << 2));
        #pragma unroll
        for (int jp = 0; jp < 4; jp++)
            ldsm_x4(b[2 * jp][0], b[2 * jp][1], b[2 * jp + 1][0], b[2 * jp + 1][1],
                    b_off + ((jp * 16 * TILE_W + k0w) << 2));
        #pragma unroll
        for (int i = 0; i < 2; i++)
            #pragma unroll
            for (int j = 0; j < 8; j++)
                mma_bf16(acc[i][j], a[i][0], a[i][1], a[i][2], a[i][3],
                         b[j][0], b[j][1]);
    }
}

// ---------------------------------------------------------------------------
// Kernel 0: zero atomically-accumulated buffers
// ---------------------------------------------------------------------------
__global__ void zero_kernel() {
    int i = blockIdx.x * 256 + threadIdx.x;
    if (i < B_ * NH_ * DM_) g_z[i] = 0.f;
    if (i < B_ * DM_) g_res[i] = 0.f;
}

// ---------------------------------------------------------------------------
// Kernel 1: Q/K projection via bf16 mma.sync (unchanged; passing since R7)
// ---------------------------------------------------------------------------
__global__ __launch_bounds__(256) void proj_kernel(
    const float* __restrict__ x,
    const float* __restrict__ wq,
    const float* __restrict__ wk)
{
    __shared__ uint32_t sA[TILE_WORDS];
    __shared__ uint32_t sB[TILE_WORDS];
    const int t = threadIdx.x;
    const int m0 = blockIdx.y << 7;
    const int n0 = blockIdx.x << 7;
    const int wid = t >> 5, lane = t & 31;
    const int wm = wid >> 1, wn = wid & 1;
    const int g = lane >> 2, tq = lane & 3;
    const uint32_t sAb = smem_u32(sA), sBb = smem_u32(sB);

    float acc[2][8][4] = {};

    #pragma unroll 1
    for (int kc = 0; kc < 8; kc++) {
        #pragma unroll
        for (int f = t; f < 2048; f += 256) {
            int row = f >> 4, q4 = f & 15;
            float4 av = *(const float4*)(
                x + (size_t)(m0 + row) * DM_ + kc * 64 + q4 * 4);
            sA[row * TILE_W + q4 * 2]     = pack_bf162(av.x, av.y);
            sA[row * TILE_W + q4 * 2 + 1] = pack_bf162(av.z, av.w);
            int n = n0 + row;
            const float* src = (n < 512) ? (wq + (size_t)n * DM_)
                                         : (wk + (size_t)(n - 512) * DM_);
            float4 bv = *(const float4*)(src + kc * 64 + q4 * 4);
            sB[row * TILE_W + q4 * 2]     = pack_bf162(bv.x, bv.y);
            sB[row * TILE_W + q4 * 2 + 1] = pack_bf162(bv.z, bv.w);
        }
        __syncthreads();
        mma_tile_core(sAb, sBb, wm, wn, lane, acc);
        __syncthreads();
    }

    #pragma unroll
    for (int i = 0; i < 2; i++) {
        #pragma unroll
        for (int rr = 0; rr < 2; rr++) {
            int r = m0 + wm * 32 + i * 16 + g + rr * 8;
            int bidx = r >> 11, l = r & 2047;
            #pragma unroll
            for (int j = 0; j < 8; j++) {
                int n = n0 + wn * 64 + j * 8 + 2 * tq;
                float v0 = acc[i][j][rr * 2 + 0];
                float v1 = acc[i][j][rr * 2 + 1];
                if (n < 512) {
                    int h = n >> 6, d = n & 63;
                    *(uint32_t*)&g_Qh[(((size_t)(bidx << 3) + h) * L_ + l) * DK_ + d] =
                        pack_bf162(v0 * QSCALE, v1 * QSCALE);
                } else {
                    int n2 = n - 512;
                    int h = n2 >> 6, d = n2 & 63;
                    *(uint32_t*)&g_Kh[(((size_t)(bidx << 3) + h) * L_ + l) * DK_ + d] =
                        pack_bf162(v0, v1);
                }
            }
        }
    }
}

// ---------------------------------------------------------------------------
// Kernel 2a: row sums. Block = (q-strip, bh). Q resident (shared, read-only).
// Two decoupled 128-thread groups: group g streams K-cols [g*64,+64) of each
// tile into its OWN double buffer with its OWN cp.async chain and named
// barrier — groups drift out of phase so HMMA overlaps EX2 across groups.
// ---------------------------------------------------------------------------
__global__ __launch_bounds__(256) void attn_rowsum_kernel()
{
    extern __shared__ uint32_t dyn[];
    uint32_t* sQ = dyn;                       // 128 x 36 resident
    __shared__ float rsum[2][128];
    const int t = threadIdx.x;
    const int lane = t & 31;
    const int g = t >> 7;                     // group (col half)
    const int gw = (t >> 5) & 3;              // warp in group == wm (q rows)
    const int tg = t & 127;
    const int q0 = blockIdx.x << 7;
    const int bh = blockIdx.y;
    const uint32_t base = smem_u32(dyn);
    const int rowl = tg >> 3, chunk = tg & 7; // stream-copy slot (16 rows x 8)

    const uint32_t* qsrc =
        (const uint32_t*)(g_Qh + (size_t)bh * L_ * DK_ + (size_t)q0 * DK_);
    const char* kbase = (const char*)(g_Kh + (size_t)bh * L_ * DK_);

    #pragma unroll
    for (int f = t; f < 1024; f += 256) {
        int rr = f >> 3, ww = (f & 7) << 2;
        *(uint4*)&sQ[rr * TILE_W + ww] = *(const uint4*)(qsrc + rr * 32 + ww);
    }

    const uint32_t hb[2] = { base + (OFF_HB(0,0) << 2) + (uint32_t)g * (2 * HBUF_WORDS << 2),
                             base + (OFF_HB(0,1) << 2) + (uint32_t)g * (2 * HBUF_WORDS << 2) };
    // issue group-half of K tile kt into buffer b
    auto issue = [&](int kt, int b) {
        const char* src = kbase + (size_t)kt * 16384 + g * 8192;
        #pragma unroll
        for (int p = 0; p < 4; p++)
            cp16(hb[b] + (((rowl + 16 * p) * TILE_W + chunk * 4) << 2),
                 src + (rowl + 16 * p) * 128 + chunk * 16);
        cp_commit();
    };
    issue(0, 0);
    issue(1, 1);
    __syncthreads();                          // sQ visible to both groups
    const int barid = g + 1;

    float rs[2][2] = {};

    #pragma unroll 1
    for (int kt = 0; kt < 16; kt++) {
        if (kt < 15) cp_wait1(); else cp_wait0();
        gbar(barid);
        float acc[2][8][4] = {};
        mma_tile_core(base, hb[kt & 1], gw, 0, lane, acc);
        #pragma unroll
        for (int i = 0; i < 2; i++)
            #pragma unroll
            for (int j = 0; j < 8; j++) {
                rs[i][0] += fast_exp2(acc[i][j][0]) + fast_exp2(acc[i][j][1]);
                rs[i][1] += fast_exp2(acc[i][j][2]) + fast_exp2(acc[i][j][3]);
            }
        gbar(barid);                          // group done reading buffer
        if (kt + 2 < 16) issue(kt + 2, kt & 1);
    }

    // reduce tq lanes; combine the two col-half groups via smem
    #pragma unroll
    for (int i = 0; i < 2; i++) {
        #pragma unroll
        for (int rr = 0; rr < 2; rr++) {
            float s = rs[i][rr];
            s += __shfl_xor_sync(0xffffffffu, s, 1);
            s += __shfl_xor_sync(0xffffffffu, s, 2);
            if ((lane & 3) == 0)
                rsum[g][gw * 32 + i * 16 + rr * 8 + (lane >> 2)] = s;
        }
    }
    __syncthreads();
    if (t < 128)
        g_ell[bh * L_ + q0 + t] = rsum[0][t] + rsum[1][t];
}

// ---------------------------------------------------------------------------
// Kernel 2b: column sums. Block = (k-strip, bh). K resident (shared).
// Group g streams Q-rows [g*64,+64) of each tile; warp coords wm=gw&1 (q),
// wn=gw>>1 (k cols). Same decoupled double-buffer scheme.
// ---------------------------------------------------------------------------
__global__ __launch_bounds__(256) void attn_colsum_kernel()
{
    extern __shared__ uint32_t dyn[];
    uint32_t* sK = dyn;                       // 128 x 36 resident
    __shared__ float colsm[128];
    const int t = threadIdx.x;
    const int lane = t & 31;
    const int g = t >> 7;                     // group (q-row half)
    const int gw = (t >> 5) & 3;
    const int wm = gw & 1, wn = gw >> 1;
    const int tg = t & 127;
    const int k0b = blockIdx.x << 7;
    const int bh = blockIdx.y;
    const uint32_t base = smem_u32(dyn);
    const int rowl = tg >> 3, chunk = tg & 7;
    const int tq = lane & 3;

    const uint32_t* ksrc =
        (const uint32_t*)(g_Kh + (size_t)bh * L_ * DK_ + (size_t)k0b * DK_);
    const char* qbase = (const char*)(g_Qh + (size_t)bh * L_ * DK_);

    #pragma unroll
    for (int f = t; f < 1024; f += 256) {
        int rr = f >> 3, ww = (f & 7) << 2;
        *(uint4*)&sK[rr * TILE_W + ww] = *(const uint4*)(ksrc + rr * 32 + ww);
    }
    if (t < 128) colsm[t] = 0.f;

    const uint32_t hb[2] = { base + (OFF_HB(0,0) << 2) + (uint32_t)g * (2 * HBUF_WORDS << 2),
                             base + (OFF_HB(0,1) << 2) + (uint32_t)g * (2 * HBUF_WORDS << 2) };
    auto issue = [&](int qt, int b) {
        const char* src = qbase + (size_t)qt * 16384 + g * 8192;
        #pragma unroll
        for (int p = 0; p < 4; p++)
            cp16(hb[b] + (((rowl + 16 * p) * TILE_W + chunk * 4) << 2),
                 src + (rowl + 16 * p) * 128 + chunk * 16);
        cp_commit();
    };
    issue(0, 0);
    issue(1, 1);
    __syncthreads();
    const int barid = g + 1;

    float cs[16];
    #pragma unroll
    for (int c = 0; c < 16; c++) cs[c] = 0.f;
    const float* ellb = g_ell + bh * L_;

    #pragma unroll 1
    for (int qt = 0; qt < 16; qt++) {
        if (qt < 15) cp_wait1(); else cp_wait0();
        gbar(barid);
        float acc[2][8][4] = {};
        mma_tile_core(hb[qt & 1], base, wm, wn, lane, acc);

        int r0 = qt * 128 + g * 64 + wm * 32 + (lane >> 2);
        float inv00 = 1.0f / ellb[r0];
        float inv01 = 1.0f / ellb[r0 + 8];
        float inv10 = 1.0f / ellb[r0 + 16];
        float inv11 = 1.0f / ellb[r0 + 24];
        #pragma unroll
        for (int j = 0; j < 8; j++) {
            cs[2 * j]     += fast_exp2(acc[0][j][0]) * inv00
                           + fast_exp2(acc[0][j][2]) * inv01
                           + fast_exp2(acc[1][j][0]) * inv10
                           + fast_exp2(acc[1][j][2]) * inv11;
            cs[2 * j + 1] += fast_exp2(acc[0][j][1]) * inv00
                           + fast_exp2(acc[0][j][3]) * inv01
                           + fast_exp2(acc[1][j][1]) * inv10
                           + fast_exp2(acc[1][j][3]) * inv11;
        }
        gbar(barid);
        if (qt + 2 < 16) issue(qt + 2, qt & 1);
    }

    // reduce over the 8 g-lanes (lane bits 2,3,4)
    #pragma unroll
    for (int off = 4; off <= 16; off <<= 1)
        #pragma unroll
        for (int c = 0; c < 16; c++)
            cs[c] += __shfl_xor_sync(0xffffffffu, cs[c], off);

    if (lane < 4) {   // q-halves + wm warps combine via atomics
        #pragma unroll
        for (int j = 0; j < 8; j++) {
            atomicAdd(&colsm[wn * 64 + j * 8 + 2 * tq],     cs[2 * j]);
            atomicAdd(&colsm[wn * 64 + j * 8 + 2 * tq + 1], cs[2 * j + 1]);
        }
    }
    __syncthreads();
    if (t < 128)
        g_P[bh * L_ + k0b + t] = colsm[t] * (1.0f / (float)L_);
}

// ---------------------------------------------------------------------------
// Kernel 4: z[b,h,m] = sum_l P[b,h,l]*x[b,l,m]; residual sums
// ---------------------------------------------------------------------------
__global__ __launch_bounds__(512) void zres_kernel(const float* __restrict__ x)
{
    __shared__ float Ps[8][128];
    const int lc = blockIdx.x;
    const int b  = blockIdx.y;
    const int t  = threadIdx.x;
    for (int i = t; i < 1024; i += 512) {
        int h = i >> 7, l = i & 127;
        Ps[h][l] = g_P[((b << 3) + h) * L_ + (lc << 7) + l];
    }
    __syncthreads();

    float zacc[8] = {};
    float racc = 0.f;
    const float* xb = x + ((size_t)b * L_ + (size_t)(lc << 7)) * DM_ + t;
    #pragma unroll 4
    for (int ll = 0; ll < 128; ll++) {
        float xv = xb[(size_t)ll * DM_];
        racc += xv;
        #pragma unroll
        for (int h = 0; h < 8; h++)
            zacc[h] += Ps[h][ll] * xv;
    }
    atomicAdd(&g_res[(b << 9) + t], racc);
    #pragma unroll
    for (int h = 0; h < 8; h++)
        atomicAdd(&g_z[(((b << 3) + h) << 9) + t], zacc[h]);
}

// ---------------------------------------------------------------------------
// Kernel 5: attn_ret, out = z@w_v^T/L, flat@w_fc^T + residual, layernorm
// ---------------------------------------------------------------------------
__global__ __launch_bounds__(512) void finalize_kernel(
    const float* __restrict__ w_v,
    const float* __restrict__ w_fc,
    const float* __restrict__ gamma,
    const float* __restrict__ beta,
    float* __restrict__ out)
{
    __shared__ float zsh[4096];
    __shared__ float flat[512];
    __shared__ float rs[16], rq[16];
    __shared__ float stats[2];
    const int b = blockIdx.x;
    const int t = threadIdx.x;

    for (int i = t; i < 4096; i += 512)
        zsh[i] = g_z[(size_t)b * 4096 + i];

    for (int k = t; k < L_; k += 512) {
        float s = 0.f;
        #pragma unroll
        for (int h = 0; h < 8; h++)
            s += g_P[((b << 3) + h) * L_ + k];
        out[4096 + b * L_ + k] = s * 0.125f;
    }
    __syncthreads();

    {
        const int h = t >> 6, dv = t & 63;
        const float4* wv4 = (const float4*)(w_v + (size_t)((h << 6) + dv) * DM_);
        const float4* z4  = (const float4*)(zsh + (h << 9));
        float ov = 0.f;
        #pragma unroll 8
        for (int m = 0; m < DM_ / 4; m++) {
            float4 a = z4[m], w = wv4[m];
            ov += a.x * w.x + a.y * w.y + a.z * w.z + a.w * w.w;
        }
        flat[(dv << 3) + h] = ov * (1.0f / (float)L_);
    }
    __syncthreads();

    float acc = g_res[(b << 9) + t] * (1.0f / (float)L_);
    {
        const float4* wf4 = (const float4*)(w_fc + (size_t)t * DM_);
        const float4* f4  = (const float4*)flat;
        #pragma unroll 8
        for (int m = 0; m < DM_ / 4; m++) {
            float4 f = f4[m], w = wf4[m];
            acc += f.x * w.x + f.y * w.y + f.z * w.z + f.w * w.w;
        }
    }

    float s1 = acc, s2 = acc * acc;
    #pragma unroll
    for (int off = 16; off; off >>= 1) {
        s1 += __shfl_xor_sync(0xffffffffu, s1, off);
        s2 += __shfl_xor_sync(0xffffffffu, s2, off);
    }
    if ((t & 31) == 0) { rs[t >> 5] = s1; rq[t >> 5] = s2; }
    __syncthreads();
    if (t == 0) {
        float S = 0.f, Q2 = 0.f;
        #pragma unroll
        for (int i = 0; i < 16; i++) { S += rs[i]; Q2 += rq[i]; }
        float mu  = S * (1.0f / 512.0f);
        float var = Q2 * (1.0f / 512.0f) - mu * mu;
        stats[0] = mu;
        stats[1] = rsqrtf(var + 1e-6f);
    }
    __syncthreads();
    out[(b << 9) + t] = (acc - stats[0]) * stats[1] * gamma[t] + beta[t];
}

// ---------------------------------------------------------------------------
extern "C" void kernel_launch(void* const* d_in, const int* in_sizes, int n_in,
                              void* d_out, int out_size)
{
    (void)in_sizes; (void)n_in; (void)out_size;
    const float* x     = (const float*)d_in[0];
    const float* w_q   = (const float*)d_in[1];
    const float* w_k   = (const float*)d_in[2];
    const float* w_v   = (const float*)d_in[3];
    const float* w_fc  = (const float*)d_in[4];
    const float* gamma = (const float*)d_in[5];
    const float* beta  = (const float*)d_in[6];
    float* out = (float*)d_out;

    cudaFuncSetAttribute(attn_rowsum_kernel,
                         cudaFuncAttributeMaxDynamicSharedMemorySize, ATTN_SMEM);
    cudaFuncSetAttribute(attn_colsum_kernel,
                         cudaFuncAttributeMaxDynamicSharedMemorySize, ATTN_SMEM);

    zero_kernel<<<144, 256>>>();
    proj_kernel<<<dim3(8, 128), 256>>>(x, w_q, w_k);
    attn_rowsum_kernel<<<dim3(16, 64), 256, ATTN_SMEM>>>();
    attn_colsum_kernel<<<dim3(16, 64), 256, ATTN_SMEM>>>();
    zres_kernel<<<dim3(16, 8), 512>>>(x);
    finalize_kernel<<<8, 512>>>(w_v, w_fc, gamma, beta, out);
}

// round 16
// speedup vs baseline: 1.1394x; 1.0606x over previous
#include <cuda_runtime.h>
#include <cuda_bf16.h>
#include <cstdint>

// Problem constants
#define B_   8
#define L_   2048
#define DM_  512
#define NH_  8
#define DK_  64
#define BH_  (B_*NH_)            // 64
// Q pre-scale: (1/sqrt(DK)) * log2(e), so epilogue is ex2.approx
#define QSCALE 0.18033688011112043f

#define TILE_W 36                 // words per smem row
#define TILE_WORDS (128 * TILE_W) // full 128-row tile
#define HBUF_WORDS (64 * TILE_W)  // half tile (64 rows)
// attention dyn smem: resident full tile + 2 groups x 2 half buffers
#define OFF_HB(g, b) (TILE_WORDS + ((g) * 2 + (b)) * HBUF_WORDS)
#define ATTN_SMEM ((TILE_WORDS + 4 * HBUF_WORDS) * 4)   // 55296 B
// proj dyn smem: A0 A1 B0 B1 full tiles
#define PROJ_SMEM (4 * TILE_WORDS * 4)                  // 73728 B

// Scratch (device globals; allocation-free kernel_launch)
__device__ __nv_bfloat16 g_xh[16384 * 512];      // bf16 x
__device__ __nv_bfloat16 g_wh[1024 * 512];       // bf16 [wq; wk]
__device__ __nv_bfloat16 g_Qh[BH_ * L_ * DK_];   // bf16, pre-scaled by QSCALE
__device__ __nv_bfloat16 g_Kh[BH_ * L_ * DK_];   // bf16
__device__ float g_ell[BH_ * L_];                // row sums of exp2(S)
__device__ float g_P[BH_ * L_];                  // pooled = colmean of softmax
__device__ float g_z[B_ * NH_ * DM_];            // z[b,h,m] = sum_k P*x
__device__ float g_res[B_ * DM_];                // sum over L of x (residual*L)

// ---------------------------------------------------------------------------
// Helpers
// ---------------------------------------------------------------------------
__device__ __forceinline__ float fast_exp2(float x) {
    float r;
    asm("ex2.approx.f32 %0, %1;" : "=f"(r) : "f"(x));
    return r;
}
__device__ __forceinline__ uint32_t pack_bf162(float lo, float hi) {
    uint32_t r;
    asm("cvt.rn.bf16x2.f32 %0, %1, %2;" : "=r"(r) : "f"(hi), "f"(lo));
    return r;
}
__device__ __forceinline__ void mma_bf16(float c[4],
    uint32_t a0, uint32_t a1, uint32_t a2, uint32_t a3,
    uint32_t b0, uint32_t b1)
{
    asm volatile(
        "mma.sync.aligned.m16n8k16.row.col.f32.bf16.bf16.f32 "
        "{%0,%1,%2,%3}, {%4,%5,%6,%7}, {%8,%9}, {%0,%1,%2,%3};\n"
        : "+f"(c[0]), "+f"(c[1]), "+f"(c[2]), "+f"(c[3])
        : "r"(a0), "r"(a1), "r"(a2), "r"(a3), "r"(b0), "r"(b1));
}
__device__ __forceinline__ void ldsm_x4(uint32_t& r0, uint32_t& r1,
                                        uint32_t& r2, uint32_t& r3,
                                        uint32_t addr)
{
    asm volatile("ldmatrix.sync.aligned.m8n8.x4.shared.b16 {%0,%1,%2,%3}, [%4];"
                 : "=r"(r0), "=r"(r1), "=r"(r2), "=r"(r3) : "r"(addr));
}
__device__ __forceinline__ uint32_t smem_u32(const void* p) {
    return (uint32_t)__cvta_generic_to_shared(p);
}
__device__ __forceinline__ void cp16(uint32_t dst, const void* src) {
    asm volatile("cp.async.cg.shared.global [%0], [%1], 16;\n"
                 :: "r"(dst), "l"(src));
}
__device__ __forceinline__ void cp_commit() {
    asm volatile("cp.async.commit_group;\n" ::: "memory");
}
__device__ __forceinline__ void cp_wait1() {
    asm volatile("cp.async.wait_group 1;\n" ::: "memory");
}
__device__ __forceinline__ void cp_wait0() {
    asm volatile("cp.async.wait_group 0;\n" ::: "memory");
}
__device__ __forceinline__ void gbar(int id) {
    asm volatile("bar.sync %0, 128;" :: "r"(id) : "memory");
}

// ---------------------------------------------------------------------------
// Full MMA tile core (proj): warp tile 32(m) x 64(n), depth 64.
// ---------------------------------------------------------------------------
__device__ __forceinline__ void mma_tile_core(
    uint32_t sQb, uint32_t sKb, int wm, int wn, int lane, float acc[2][8][4])
{
    const uint32_t a_off =
        sQb + (((wm * 32 + (lane & 15)) * TILE_W + (lane >> 4) * 4) << 2);
    const uint32_t b_off =
        sKb + (((wn * 64 + ((lane >> 4) << 3) + (lane & 7)) * TILE_W
                + ((lane >> 3) & 1) * 4) << 2);
    #pragma unroll
    for (int k0w = 0; k0w < 32; k0w += 8) {
        uint32_t a[2][4], b[8][2];
        #pragma unroll
        for (int i = 0; i < 2; i++)
            ldsm_x4(a[i][0], a[i][1], a[i][2], a[i][3],
                    a_off + ((i * 16 * TILE_W + k0w) << 2));
        #pragma unroll
        for (int jp = 0; jp < 4; jp++)
            ldsm_x4(b[2 * jp][0], b[2 * jp][1], b[2 * jp + 1][0], b[2 * jp + 1][1],
                    b_off + ((jp * 16 * TILE_W + k0w) << 2));
        #pragma unroll
        for (int i = 0; i < 2; i++)
            #pragma unroll
            for (int j = 0; j < 8; j++)
                mma_bf16(acc[i][j], a[i][0], a[i][1], a[i][2], a[i][3],
                         b[j][0], b[j][1]);
    }
}

// Half core: 4 n-subtiles (32 cols) at half nh. acc[2][4][4] = 32 regs.
__device__ __forceinline__ void mma_tile_half(
    uint32_t sQb, uint32_t sKb, int wm, int wn, int nh, int lane,
    float acc[2][4][4])
{
    const uint32_t a_off =
        sQb + (((wm * 32 + (lane & 15)) * TILE_W + (lane >> 4) * 4) << 2);
    const uint32_t b_off =
        sKb + (((wn * 64 + nh * 32 + ((lane >> 4) << 3) + (lane & 7)) * TILE_W
                + ((lane >> 3) & 1) * 4) << 2);
    #pragma unroll
    for (int k0w = 0; k0w < 32; k0w += 8) {
        uint32_t a[2][4], b[4][2];
        #pragma unroll
        for (int i = 0; i < 2; i++)
            ldsm_x4(a[i][0], a[i][1], a[i][2], a[i][3],
                    a_off + ((i * 16 * TILE_W + k0w) << 2));
        #pragma unroll
        for (int jp = 0; jp < 2; jp++)
            ldsm_x4(b[2 * jp][0], b[2 * jp][1], b[2 * jp + 1][0], b[2 * jp + 1][1],
                    b_off + ((jp * 16 * TILE_W + k0w) << 2));
        #pragma unroll
        for (int i = 0; i < 2; i++)
            #pragma unroll
            for (int j = 0; j < 4; j++)
                mma_bf16(acc[i][j], a[i][0], a[i][1], a[i][2], a[i][3],
                         b[j][0], b[j][1]);
    }
}

// ---------------------------------------------------------------------------
// Kernel 0a: zero atomically-accumulated buffers
// ---------------------------------------------------------------------------
__global__ void zero_kernel() {
    int i = blockIdx.x * 256 + threadIdx.x;
    if (i < B_ * NH_ * DM_) g_z[i] = 0.f;
    if (i < B_ * DM_) g_res[i] = 0.f;
}

// ---------------------------------------------------------------------------
// Kernel 0b: convert x / [wq;wk] to bf16 once
// ---------------------------------------------------------------------------
__global__ __launch_bounds__(256) void convert_kernel(
    const float* __restrict__ x,
    const float* __restrict__ wq,
    const float* __restrict__ wk)
{
    size_t i = ((size_t)blockIdx.x * 256 + threadIdx.x) * 4;
    const size_t XN = (size_t)16384 * 512;       // 8388608
    if (i < XN) {
        float4 v = *(const float4*)(x + i);
        *(uint32_t*)&g_xh[i]     = pack_bf162(v.x, v.y);
        *(uint32_t*)&g_xh[i + 2] = pack_bf162(v.z, v.w);
    } else {
        size_t j = i - XN;
        if (j < (size_t)1024 * 512) {
            const float* src = (j < (size_t)512 * 512) ? (wq + j)
                                                       : (wk + j - (size_t)512 * 512);
            float4 v = *(const float4*)src;
            *(uint32_t*)&g_wh[j]     = pack_bf162(v.x, v.y);
            *(uint32_t*)&g_wh[j + 2] = pack_bf162(v.z, v.w);
        }
    }
}

// ---------------------------------------------------------------------------
// Kernel 1: Q/K projection, bf16 inputs, cp.async double-buffered pipeline.
// ---------------------------------------------------------------------------
__global__ __launch_bounds__(256) void proj_kernel()
{
    extern __shared__ uint32_t dyn[];
    const uint32_t base = smem_u32(dyn);
    const int t = threadIdx.x;
    const int m0 = blockIdx.y << 7;
    const int n0 = blockIdx.x << 7;
    const int wid = t >> 5, lane = t & 31;
    const int wm = wid >> 1, wn = wid & 1;
    const int g = lane >> 2, tq = lane & 3;
    const int rowl = t >> 3, chunk = t & 7;

    const uint32_t sAb[2] = { base, base + (TILE_WORDS << 2) };
    const uint32_t sBb[2] = { base + (2 * TILE_WORDS << 2),
                              base + (3 * TILE_WORDS << 2) };

    auto issue = [&](int kc, int b) {
        const char* asrc = (const char*)g_xh + (size_t)m0 * 1024 + (size_t)kc * 128;
        const char* bsrc = (const char*)g_wh + (size_t)n0 * 1024 + (size_t)kc * 128;
        #pragma unroll
        for (int p = 0; p < 4; p++) {
            int r = rowl + 32 * p;
            cp16(sAb[b] + ((r * TILE_W + chunk * 4) << 2),
                 asrc + (size_t)r * 1024 + chunk * 16);
            cp16(sBb[b] + ((r * TILE_W + chunk * 4) << 2),
                 bsrc + (size_t)r * 1024 + chunk * 16);
        }
        cp_commit();
    };

    float acc[2][8][4] = {};
    issue(0, 0);
    issue(1, 1);

    #pragma unroll 1
    for (int kc = 0; kc < 8; kc++) {
        if (kc < 7) cp_wait1(); else cp_wait0();
        __syncthreads();
        mma_tile_core(sAb[kc & 1], sBb[kc & 1], wm, wn, lane, acc);
        __syncthreads();
        if (kc + 2 < 8) issue(kc + 2, kc & 1);
    }

    #pragma unroll
    for (int i = 0; i < 2; i++) {
        #pragma unroll
        for (int rr = 0; rr < 2; rr++) {
            int r = m0 + wm * 32 + i * 16 + g + rr * 8;
            int bidx = r >> 11, l = r & 2047;
            #pragma unroll
            for (int j = 0; j < 8; j++) {
                int n = n0 + wn * 64 + j * 8 + 2 * tq;
                float v0 = acc[i][j][rr * 2 + 0];
                float v1 = acc[i][j][rr * 2 + 1];
                if (n < 512) {
                    int h = n >> 6, d = n & 63;
                    *(uint32_t*)&g_Qh[(((size_t)(bidx << 3) + h) * L_ + l) * DK_ + d] =
                        pack_bf162(v0 * QSCALE, v1 * QSCALE);
                } else {
                    int n2 = n - 512;
                    int h = n2 >> 6, d = n2 & 63;
                    *(uint32_t*)&g_Kh[(((size_t)(bidx << 3) + h) * L_ + l) * DK_ + d] =
                        pack_bf162(v0, v1);
                }
            }
        }
    }
}

// ---------------------------------------------------------------------------
// Kernel 2a: row sums. Q resident; 2 decoupled 128-thread groups stream
// K-col halves; per-tile work split into two n-halves so warps alternate
// HMMA / EX2 phases at fine granularity.
// ---------------------------------------------------------------------------
__global__ __launch_bounds__(256) void attn_rowsum_kernel()
{
    extern __shared__ uint32_t dyn[];
    uint32_t* sQ = dyn;
    __shared__ float rsum[2][128];
    const int t = threadIdx.x;
    const int lane = t & 31;
    const int g = t >> 7;
    const int gw = (t >> 5) & 3;
    const int tg = t & 127;
    const int q0 = blockIdx.x << 7;
    const int bh = blockIdx.y;
    const uint32_t base = smem_u32(dyn);
    const int rowl = tg >> 3, chunk = tg & 7;

    const uint32_t* qsrc =
        (const uint32_t*)(g_Qh + (size_t)bh * L_ * DK_ + (size_t)q0 * DK_);
    const char* kbase = (const char*)(g_Kh + (size_t)bh * L_ * DK_);

    #pragma unroll
    for (int f = t; f < 1024; f += 256) {
        int rr = f >> 3, ww = (f & 7) << 2;
        *(uint4*)&sQ[rr * TILE_W + ww] = *(const uint4*)(qsrc + rr * 32 + ww);
    }

    const uint32_t hb[2] = { base + (OFF_HB(0,0) << 2) + (uint32_t)g * (2 * HBUF_WORDS << 2),
                             base + (OFF_HB(0,1) << 2) + (uint32_t)g * (2 * HBUF_WORDS << 2) };
    auto issue = [&](int kt, int b) {
        const char* src = kbase + (size_t)kt * 16384 + g * 8192;
        #pragma unroll
        for (int p = 0; p < 4; p++)
            cp16(hb[b] + (((rowl + 16 * p) * TILE_W + chunk * 4) << 2),
                 src + (rowl + 16 * p) * 128 + chunk * 16);
        cp_commit();
    };
    issue(0, 0);
    issue(1, 1);
    __syncthreads();
    const int barid = g + 1;

    float rs[2][2] = {};

    #pragma unroll 1
    for (int kt = 0; kt < 16; kt++) {
        if (kt < 15) cp_wait1(); else cp_wait0();
        gbar(barid);
        #pragma unroll
        for (int nh = 0; nh < 2; nh++) {
            float acc[2][4][4] = {};
            mma_tile_half(base, hb[kt & 1], gw, 0, nh, lane, acc);
            #pragma unroll
            for (int i = 0; i < 2; i++)
                #pragma unroll
                for (int j = 0; j < 4; j++) {
                    rs[i][0] += fast_exp2(acc[i][j][0]) + fast_exp2(acc[i][j][1]);
                    rs[i][1] += fast_exp2(acc[i][j][2]) + fast_exp2(acc[i][j][3]);
                }
        }
        gbar(barid);
        if (kt + 2 < 16) issue(kt + 2, kt & 1);
    }

    #pragma unroll
    for (int i = 0; i < 2; i++) {
        #pragma unroll
        for (int rr = 0; rr < 2; rr++) {
            float s = rs[i][rr];
            s += __shfl_xor_sync(0xffffffffu, s, 1);
            s += __shfl_xor_sync(0xffffffffu, s, 2);
            if ((lane & 3) == 0)
                rsum[g][gw * 32 + i * 16 + rr * 8 + (lane >> 2)] = s;
        }
    }
    __syncthreads();
    if (t < 128)
        g_ell[bh * L_ + q0 + t] = rsum[0][t] + rsum[1][t];
}

// ---------------------------------------------------------------------------
// Kernel 2b: column sums. K resident; groups stream Q-row halves; per-tile
// half-split HMMA/EX2 interleave; cs[16] reindexed per half.
// ---------------------------------------------------------------------------
__global__ __launch_bounds__(256) void attn_colsum_kernel()
{
    extern __shared__ uint32_t dyn[];
    uint32_t* sK = dyn;
    __shared__ float colsm[128];
    const int t = threadIdx.x;
    const int lane = t & 31;
    const int g = t >> 7;
    const int gw = (t >> 5) & 3;
    const int wm = gw & 1, wn = gw >> 1;
    const int tg = t & 127;
    const int k0b = blockIdx.x << 7;
    const int bh = blockIdx.y;
    const uint32_t base = smem_u32(dyn);
    const int rowl = tg >> 3, chunk = tg & 7;
    const int tq = lane & 3;

    const uint32_t* ksrc =
        (const uint32_t*)(g_Kh + (size_t)bh * L_ * DK_ + (size_t)k0b * DK_);
    const char* qbase = (const char*)(g_Qh + (size_t)bh * L_ * DK_);

    #pragma unroll
    for (int f = t; f < 1024; f += 256) {
        int rr = f >> 3, ww = (f & 7) << 2;
        *(uint4*)&sK[rr * TILE_W + ww] = *(const uint4*)(ksrc + rr * 32 + ww);
    }
    if (t < 128) colsm[t] = 0.f;

    const uint32_t hb[2] = { base + (OFF_HB(0,0) << 2) + (uint32_t)g * (2 * HBUF_WORDS << 2),
                             base + (OFF_HB(0,1) << 2) + (uint32_t)g * (2 * HBUF_WORDS << 2) };
    auto issue = [&](int qt, int b) {
        const char* src = qbase + (size_t)qt * 16384 + g * 8192;
        #pragma unroll
        for (int p = 0; p < 4; p++)
            cp16(hb[b] + (((rowl + 16 * p) * TILE_W + chunk * 4) << 2),
                 src + (rowl + 16 * p) * 128 + chunk * 16);
        cp_commit();
    };
    issue(0, 0);
    issue(1, 1);
    __syncthreads();
    const int barid = g + 1;

    float cs[16];
    #pragma unroll
    for (int c = 0; c < 16; c++) cs[c] = 0.f;
    const float* ellb = g_ell + bh * L_;

    #pragma unroll 1
    for (int qt = 0; qt < 16; qt++) {
        if (qt < 15) cp_wait1(); else cp_wait0();
        gbar(barid);

        int r0 = qt * 128 + g * 64 + wm * 32 + (lane >> 2);
        float inv00 = 1.0f / ellb[r0];
        float inv01 = 1.0f / ellb[r0 + 8];
        float inv10 = 1.0f / ellb[r0 + 16];
        float inv11 = 1.0f / ellb[r0 + 24];

        #pragma unroll
        for (int nh = 0; nh < 2; nh++) {
            float acc[2][4][4] = {};
            mma_tile_half(hb[qt & 1], base, wm, wn, nh, lane, acc);
            #pragma unroll
            for (int j = 0; j < 4; j++) {
                cs[nh * 8 + 2 * j]     += fast_exp2(acc[0][j][0]) * inv00
                                        + fast_exp2(acc[0][j][2]) * inv01
                                        + fast_exp2(acc[1][j][0]) * inv10
                                        + fast_exp2(acc[1][j][2]) * inv11;
                cs[nh * 8 + 2 * j + 1] += fast_exp2(acc[0][j][1]) * inv00
                                        + fast_exp2(acc[0][j][3]) * inv01
                                        + fast_exp2(acc[1][j][1]) * inv10
                                        + fast_exp2(acc[1][j][3]) * inv11;
            }
        }
        gbar(barid);
        if (qt + 2 < 16) issue(qt + 2, qt & 1);
    }

    // reduce over the 8 g-lanes (lane bits 2,3,4)
    #pragma unroll
    for (int off = 4; off <= 16; off <<= 1)
        #pragma unroll
        for (int c = 0; c < 16; c++)
            cs[c] += __shfl_xor_sync(0xffffffffu, cs[c], off);

    if (lane < 4) {   // tq == lane; cols = wn*64 + nh*32 + j*8 + 2tq + {0,1}
        #pragma unroll
        for (int nh = 0; nh < 2; nh++)
            #pragma unroll
            for (int j = 0; j < 4; j++) {
                atomicAdd(&colsm[wn * 64 + nh * 32 + j * 8 + 2 * tq],
                          cs[nh * 8 + 2 * j]);
                atomicAdd(&colsm[wn * 64 + nh * 32 + j * 8 + 2 * tq + 1],
                          cs[nh * 8 + 2 * j + 1]);
            }
    }
    __syncthreads();
    if (t < 128)
        g_P[bh * L_ + k0b + t] = colsm[t] * (1.0f / (float)L_);
}

// ---------------------------------------------------------------------------
// Kernel 4: z[b,h,m] = sum_l P[b,h,l]*x[b,l,m]; residual sums
// ---------------------------------------------------------------------------
__global__ __launch_bounds__(512) void zres_kernel(const float* __restrict__ x)
{
    __shared__ float Ps[8][128];
    const int lc = blockIdx.x;
    const int b  = blockIdx.y;
    const int t  = threadIdx.x;
    for (int i = t; i < 1024; i += 512) {
        int h = i >> 7, l = i & 127;
        Ps[h][l] = g_P[((b << 3) + h) * L_ + (lc << 7) + l];
    }
    __syncthreads();

    float zacc[8] = {};
    float racc = 0.f;
    const float* xb = x + ((size_t)b * L_ + (size_t)(lc << 7)) * DM_ + t;
    #pragma unroll 4
    for (int ll = 0; ll < 128; ll++) {
        float xv = xb[(size_t)ll * DM_];
        racc += xv;
        #pragma unroll
        for (int h = 0; h < 8; h++)
            zacc[h] += Ps[h][ll] * xv;
    }
    atomicAdd(&g_res[(b << 9) + t], racc);
    #pragma unroll
    for (int h = 0; h < 8; h++)
        atomicAdd(&g_z[(((b << 3) + h) << 9) + t], zacc[h]);
}

// ---------------------------------------------------------------------------
// Kernel 5: attn_ret, out = z@w_v^T/L, flat@w_fc^T + residual, layernorm
// ---------------------------------------------------------------------------
__global__ __launch_bounds__(512) void finalize_kernel(
    const float* __restrict__ w_v,
    const float* __restrict__ w_fc,
    const float* __restrict__ gamma,
    const float* __restrict__ beta,
    float* __restrict__ out)
{
    __shared__ float zsh[4096];
    __shared__ float flat[512];
    __shared__ float rs[16], rq[16];
    __shared__ float stats[2];
    const int b = blockIdx.x;
    const int t = threadIdx.x;

    for (int i = t; i < 4096; i += 512)
        zsh[i] = g_z[(size_t)b * 4096 + i];

    for (int k = t; k < L_; k += 512) {
        float s = 0.f;
        #pragma unroll
        for (int h = 0; h < 8; h++)
            s += g_P[((b << 3) + h) * L_ + k];
        out[4096 + b * L_ + k] = s * 0.125f;
    }
    __syncthreads();

    {
        const int h = t >> 6, dv = t & 63;
        const float4* wv4 = (const float4*)(w_v + (size_t)((h << 6) + dv) * DM_);
        const float4* z4  = (const float4*)(zsh + (h << 9));
        float ov = 0.f;
        #pragma unroll 8
        for (int m = 0; m < DM_ / 4; m++) {
            float4 a = z4[m], w = wv4[m];
            ov += a.x * w.x + a.y * w.y + a.z * w.z + a.w * w.w;
        }
        flat[(dv << 3) + h] = ov * (1.0f / (float)L_);
    }
    __syncthreads();

    float acc = g_res[(b << 9) + t] * (1.0f / (float)L_);
    {
        const float4* wf4 = (const float4*)(w_fc + (size_t)t * DM_);
        const float4* f4  = (const float4*)flat;
        #pragma unroll 8
        for (int m = 0; m < DM_ / 4; m++) {
            float4 f = f4[m], w = wf4[m];
            acc += f.x * w.x + f.y * w.y + f.z * w.z + f.w * w.w;
        }
    }

    float s1 = acc, s2 = acc * acc;
    #pragma unroll
    for (int off = 16; off; off >>= 1) {
        s1 += __shfl_xor_sync(0xffffffffu, s1, off);
        s2 += __shfl_xor_sync(0xffffffffu, s2, off);
    }
    if ((t & 31) == 0) { rs[t >> 5] = s1; rq[t >> 5] = s2; }
    __syncthreads();
    if (t == 0) {
        float S = 0.f, Q2 = 0.f;
        #pragma unroll
        for (int i = 0; i < 16; i++) { S += rs[i]; Q2 += rq[i]; }
        float mu  = S * (1.0f / 512.0f);
        float var = Q2 * (1.0f / 512.0f) - mu * mu;
        stats[0] = mu;
        stats[1] = rsqrtf(var + 1e-6f);
    }
    __syncthreads();
    out[(b << 9) + t] = (acc - stats[0]) * stats[1] * gamma[t] + beta[t];
}

// ---------------------------------------------------------------------------
extern "C" void kernel_launch(void* const* d_in, const int* in_sizes, int n_in,
                              void* d_out, int out_size)
{
    (void)in_sizes; (void)n_in; (void)out_size;
    const float* x     = (const float*)d_in[0];
    const float* w_q   = (const float*)d_in[1];
    const float* w_k   = (const float*)d_in[2];
    const float* w_v   = (const float*)d_in[3];
    const float* w_fc  = (const float*)d_in[4];
    const float* gamma = (const float*)d_in[5];
    const float* beta  = (const float*)d_in[6];
    float* out = (float*)d_out;

    cudaFuncSetAttribute(proj_kernel,
                         cudaFuncAttributeMaxDynamicSharedMemorySize, PROJ_SMEM);
    cudaFuncSetAttribute(attn_rowsum_kernel,
                         cudaFuncAttributeMaxDynamicSharedMemorySize, ATTN_SMEM);
    cudaFuncSetAttribute(attn_colsum_kernel,
                         cudaFuncAttributeMaxDynamicSharedMemorySize, ATTN_SMEM);

    zero_kernel<<<144, 256>>>();
    convert_kernel<<<8704, 256>>>(x, w_q, w_k);
    proj_kernel<<<dim3(8, 128), 256, PROJ_SMEM>>>();
    attn_rowsum_kernel<<<dim3(16, 64), 256, ATTN_SMEM>>>();
    attn_colsum_kernel<<<dim3(16, 64), 256, ATTN_SMEM>>>();
    zres_kernel<<<dim3(16, 8), 512>>>(x);
    finalize_kernel<<<8, 512>>>(w_v, w_fc, gamma, beta, out);
}